// round 9
// baseline (speedup 1.0000x reference)
#include <cuda_runtime.h>
#include <cstdint>
#include <cstddef>

#define NTN   32768
#define CCH   128
#define BATCH 64
#define NNODE 512
#define NH    4
#define DHEAD 32
#define NEDGE 524288
#define EPSBN 1e-5f

// ---------------- scratch (static device globals; no allocation) ----------------
__device__ int   d_cnt[NTN];
__device__ int   d_offs[NTN + 1];
__device__ int   d_cursor[NTN];
__device__ int   d_ebin[NEDGE];
__device__ float d_agg[NTN * CCH];
__device__ float d_h1[NTN * CCH];
__device__ float d_qkv[NTN * 3 * CCH];
__device__ float d_ao[NTN * CCH];
__device__ float d_h2[NTN * CCH];
__device__ float d_out1[NTN * CCH];
__device__ float d_hid[NTN * 2 * CCH];
__device__ float d_out2[NTN * CCH];
__device__ float d_stats[6 * CCH];

// ---------------- init ----------------
__global__ void k_init() {
    int i = blockIdx.x * blockDim.x + threadIdx.x;
    if (i < NTN) d_cnt[i] = 0;
    if (i < 6 * CCH) d_stats[i] = 0.f;
}

__global__ void k_count(const int* __restrict__ ei) {
    int e = blockIdx.x * blockDim.x + threadIdx.x;
    if (e < NEDGE) atomicAdd(&d_cnt[ei[NEDGE + e]], 1);
}

__global__ void k_scan() {
    __shared__ int part[1024];
    int tid = threadIdx.x;
    int base = tid * 32;
    int local[32];
    int s = 0;
    #pragma unroll
    for (int i = 0; i < 32; i++) { local[i] = d_cnt[base + i]; s += local[i]; }
    part[tid] = s;
    __syncthreads();
    for (int off = 1; off < 1024; off <<= 1) {
        int v = (tid >= off) ? part[tid - off] : 0;
        __syncthreads();
        part[tid] += v;
        __syncthreads();
    }
    int run = (tid == 0) ? 0 : part[tid - 1];
    #pragma unroll
    for (int i = 0; i < 32; i++) {
        d_offs[base + i] = run;
        d_cursor[base + i] = run;
        run += local[i];
    }
    if (tid == 1023) d_offs[NTN] = run;
}

__global__ void k_bin(const int* __restrict__ ei) {
    int e = blockIdx.x * blockDim.x + threadIdx.x;
    if (e < NEDGE) {
        int src = ei[e];
        int dst = ei[NEDGE + e];
        int pos = atomicAdd(&d_cursor[dst], 1);
        d_ebin[pos] = src;
    }
}

__global__ void k_agg(const float* __restrict__ x) {
    int warp = (blockIdx.x * blockDim.x + threadIdx.x) >> 5;
    int lane = threadIdx.x & 31;
    if (warp >= NTN) return;
    int beg = d_offs[warp], end = d_offs[warp + 1];
    const float4* x4 = (const float4*)x;
    float4 acc = make_float4(0.f, 0.f, 0.f, 0.f);
    for (int e = beg; e < end; e++) {
        int s = __ldg(&d_ebin[e]);
        float4 v = x4[(size_t)s * 32 + lane];
        acc.x += v.x; acc.y += v.y; acc.z += v.z; acc.w += v.w;
    }
    int deg = end - beg;
    float inv = 1.f / (float)(deg > 0 ? deg : 1);
    acc.x *= inv; acc.y *= inv; acc.z *= inv; acc.w *= inv;
    ((float4*)d_agg)[(size_t)warp * 32 + lane] = acc;
}

// ---------------- tf32 helper ----------------
__device__ __forceinline__ float to_tf32(float x) {
    uint32_t u;
    asm("cvt.rna.tf32.f32 %0, %1;" : "=r"(u) : "f"(x));
    return __uint_as_float(u);
}

// ---------------- tf32 GEMM: 128x128 CTA, 512 thr, 16 warps, 32x32 warp tile ----------------
// out[M,NC] = A[M,K] @ W[NC,K]^T + bias (+resid)(+relu)(+col stats)
#define GBK 32
__global__ void __launch_bounds__(512) k_gemm2(
    const float* __restrict__ A, const float* __restrict__ W,
    const float* __restrict__ bias, const float* __restrict__ resid,
    float* __restrict__ out, float* __restrict__ ssum, float* __restrict__ ssq,
    int M, int NC, int K, int relu)
{
    __shared__ float As[128][GBK + 4];
    __shared__ float Bs[128][GBK + 4];
    int row0 = blockIdx.x * 128;
    int col0 = blockIdx.y * 128;
    int tid = threadIdx.x;
    int wid = tid >> 5;
    int lane = tid & 31;
    int g = lane >> 2, tg = lane & 3;
    int wm = (wid & 3) * 32;          // 4 warp-rows of 32
    int wn = (wid >> 2) * 32;         // 4 warp-cols of 32

    int m_base = tid >> 3;            // 0..63
    int kq = (tid & 7) * 4;

    float c[2][4][4];
    #pragma unroll
    for (int i = 0; i < 2; i++)
        #pragma unroll
        for (int j = 0; j < 4; j++)
            #pragma unroll
            for (int l = 0; l < 4; l++) c[i][j][l] = 0.f;

    float4 pa[2], pb[2];
    #pragma unroll
    for (int it = 0; it < 2; it++) {
        pa[it] = *(const float4*)&A[(size_t)(row0 + m_base + it * 64) * K + kq];
        pb[it] = *(const float4*)&W[(size_t)(col0 + m_base + it * 64) * K + kq];
    }

    for (int kb = 0; kb < K; kb += GBK) {
        #pragma unroll
        for (int it = 0; it < 2; it++) {
            float4 v = pa[it];
            v.x = to_tf32(v.x); v.y = to_tf32(v.y); v.z = to_tf32(v.z); v.w = to_tf32(v.w);
            *(float4*)&As[m_base + it * 64][kq] = v;
            float4 w = pb[it];
            w.x = to_tf32(w.x); w.y = to_tf32(w.y); w.z = to_tf32(w.z); w.w = to_tf32(w.w);
            *(float4*)&Bs[m_base + it * 64][kq] = w;
        }
        __syncthreads();
        if (kb + GBK < K) {
            #pragma unroll
            for (int it = 0; it < 2; it++) {
                pa[it] = *(const float4*)&A[(size_t)(row0 + m_base + it * 64) * K + kb + GBK + kq];
                pb[it] = *(const float4*)&W[(size_t)(col0 + m_base + it * 64) * K + kb + GBK + kq];
            }
        }
        #pragma unroll
        for (int ks = 0; ks < 4; ks++) {
            int k0 = ks * 8;
            uint32_t b[4][2];
            #pragma unroll
            for (int nt = 0; nt < 4; nt++) {
                int n = wn + nt * 8 + g;
                b[nt][0] = __float_as_uint(Bs[n][k0 + tg]);
                b[nt][1] = __float_as_uint(Bs[n][k0 + tg + 4]);
            }
            #pragma unroll
            for (int mt = 0; mt < 2; mt++) {
                int m = wm + mt * 16 + g;
                uint32_t a0 = __float_as_uint(As[m][k0 + tg]);
                uint32_t a1 = __float_as_uint(As[m + 8][k0 + tg]);
                uint32_t a2 = __float_as_uint(As[m][k0 + tg + 4]);
                uint32_t a3 = __float_as_uint(As[m + 8][k0 + tg + 4]);
                #pragma unroll
                for (int nt = 0; nt < 4; nt++) {
                    asm volatile(
                        "mma.sync.aligned.m16n8k8.row.col.f32.tf32.tf32.f32 "
                        "{%0,%1,%2,%3}, {%4,%5,%6,%7}, {%8,%9}, {%0,%1,%2,%3};"
                        : "+f"(c[mt][nt][0]), "+f"(c[mt][nt][1]),
                          "+f"(c[mt][nt][2]), "+f"(c[mt][nt][3])
                        : "r"(a0), "r"(a1), "r"(a2), "r"(a3),
                          "r"(b[nt][0]), "r"(b[nt][1]));
                }
            }
        }
        __syncthreads();
    }

    // epilogue (+optional fused column stats)
    float s0[4] = {0.f, 0.f, 0.f, 0.f}, s1[4] = {0.f, 0.f, 0.f, 0.f};
    float q0[4] = {0.f, 0.f, 0.f, 0.f}, q1[4] = {0.f, 0.f, 0.f, 0.f};
    #pragma unroll
    for (int mt = 0; mt < 2; mt++) {
        #pragma unroll
        for (int nt = 0; nt < 4; nt++) {
            int r = row0 + wm + mt * 16 + g;
            int cc = col0 + wn + nt * 8 + 2 * tg;
            float2 bv = *(const float2*)&bias[cc];
            float v0 = c[mt][nt][0] + bv.x;
            float v1 = c[mt][nt][1] + bv.y;
            float v2 = c[mt][nt][2] + bv.x;
            float v3 = c[mt][nt][3] + bv.y;
            if (resid) {
                float2 r0v = *(const float2*)&resid[(size_t)r * NC + cc];
                float2 r1v = *(const float2*)&resid[(size_t)(r + 8) * NC + cc];
                v0 += r0v.x; v1 += r0v.y; v2 += r1v.x; v3 += r1v.y;
            }
            if (relu) {
                v0 = fmaxf(v0, 0.f); v1 = fmaxf(v1, 0.f);
                v2 = fmaxf(v2, 0.f); v3 = fmaxf(v3, 0.f);
            }
            *(float2*)&out[(size_t)r * NC + cc] = make_float2(v0, v1);
            *(float2*)&out[(size_t)(r + 8) * NC + cc] = make_float2(v2, v3);
            if (ssum) {
                s0[nt] += v0 + v2;
                s1[nt] += v1 + v3;
                q0[nt] += v0 * v0 + v2 * v2;
                q1[nt] += v1 * v1 + v3 * v3;
            }
        }
    }
    if (ssum) {
        #pragma unroll
        for (int nt = 0; nt < 4; nt++) {
            #pragma unroll
            for (int off = 4; off <= 16; off <<= 1) {
                s0[nt] += __shfl_xor_sync(0xffffffffu, s0[nt], off);
                s1[nt] += __shfl_xor_sync(0xffffffffu, s1[nt], off);
                q0[nt] += __shfl_xor_sync(0xffffffffu, q0[nt], off);
                q1[nt] += __shfl_xor_sync(0xffffffffu, q1[nt], off);
            }
            if (lane < 4) {
                int cc = col0 + wn + nt * 8 + 2 * tg;
                atomicAdd(&ssum[cc], s0[nt]);
                atomicAdd(&ssq[cc],  q0[nt]);
                atomicAdd(&ssum[cc + 1], s1[nt]);
                atomicAdd(&ssq[cc + 1],  q1[nt]);
            }
        }
    }
}

// ---------------- tensor-core flash attention (validated R5) ----------------
#define KT 64
#define KS_PAD 36
#define VS_PAD 40
#define PS_PAD 68
#define ATTN_SMEM ((KT * KS_PAD + KT * VS_PAD + 8 * 16 * PS_PAD) * 4)
__global__ void __launch_bounds__(256) k_attn_tc(const float* __restrict__ qkv,
                                                 float* __restrict__ ao)
{
    extern __shared__ float sm[];
    float* Ks = sm;
    float* Vs = Ks + KT * KS_PAD;
    int tid = threadIdx.x;
    int wid = tid >> 5;
    int lane = tid & 31;
    int g = lane >> 2, tg = lane & 3;
    float* Ps = Vs + KT * VS_PAD + wid * 16 * PS_PAD;

    int blk = blockIdx.x;
    int qt = blk & 3;
    int bh = blk >> 2;
    int b = bh >> 2;
    int h = bh & 3;
    const float* base = qkv + (size_t)b * NNODE * (3 * CCH);
    int qrow0 = qt * 128 + wid * 16;
    const float SCALE = 0.1767766952966369f;

    uint32_t qa[4][4];
    #pragma unroll
    for (int kc = 0; kc < 4; kc++) {
        const float* q0 = base + (size_t)(qrow0 + g) * (3 * CCH) + h * DHEAD + 8 * kc;
        const float* q1 = base + (size_t)(qrow0 + g + 8) * (3 * CCH) + h * DHEAD + 8 * kc;
        qa[kc][0] = __float_as_uint(to_tf32(q0[tg]));
        qa[kc][1] = __float_as_uint(to_tf32(q1[tg]));
        qa[kc][2] = __float_as_uint(to_tf32(q0[tg + 4]));
        qa[kc][3] = __float_as_uint(to_tf32(q1[tg + 4]));
    }

    float m0 = -1e30f, m1 = -1e30f, l0 = 0.f, l1 = 0.f;
    float o[4][4];
    #pragma unroll
    for (int i = 0; i < 4; i++)
        #pragma unroll
        for (int j = 0; j < 4; j++) o[i][j] = 0.f;

    for (int kt = 0; kt < NNODE / KT; kt++) {
        #pragma unroll
        for (int it = 0; it < 2; it++) {
            int idx = tid + it * 256;
            int row = idx >> 3;
            int c4 = (idx & 7) * 4;
            const float* krow = base + (size_t)(kt * KT + row) * (3 * CCH) + CCH + h * DHEAD;
            const float* vrow = base + (size_t)(kt * KT + row) * (3 * CCH) + 2 * CCH + h * DHEAD;
            float4 kv = *(const float4*)(krow + c4);
            float4 vv = *(const float4*)(vrow + c4);
            kv.x = to_tf32(kv.x); kv.y = to_tf32(kv.y); kv.z = to_tf32(kv.z); kv.w = to_tf32(kv.w);
            vv.x = to_tf32(vv.x); vv.y = to_tf32(vv.y); vv.z = to_tf32(vv.z); vv.w = to_tf32(vv.w);
            *(float4*)(Ks + row * KS_PAD + c4) = kv;
            *(float4*)(Vs + row * VS_PAD + c4) = vv;
        }
        __syncthreads();

        float s[8][4];
        #pragma unroll
        for (int nt = 0; nt < 8; nt++)
            #pragma unroll
            for (int j = 0; j < 4; j++) s[nt][j] = 0.f;
        #pragma unroll
        for (int kc = 0; kc < 4; kc++) {
            #pragma unroll
            for (int nt = 0; nt < 8; nt++) {
                uint32_t b0 = __float_as_uint(Ks[(nt * 8 + g) * KS_PAD + 8 * kc + tg]);
                uint32_t b1 = __float_as_uint(Ks[(nt * 8 + g) * KS_PAD + 8 * kc + tg + 4]);
                asm volatile(
                    "mma.sync.aligned.m16n8k8.row.col.f32.tf32.tf32.f32 "
                    "{%0,%1,%2,%3}, {%4,%5,%6,%7}, {%8,%9}, {%0,%1,%2,%3};"
                    : "+f"(s[nt][0]), "+f"(s[nt][1]), "+f"(s[nt][2]), "+f"(s[nt][3])
                    : "r"(qa[kc][0]), "r"(qa[kc][1]), "r"(qa[kc][2]), "r"(qa[kc][3]),
                      "r"(b0), "r"(b1));
            }
        }
        float mx0 = -1e30f, mx1 = -1e30f;
        #pragma unroll
        for (int nt = 0; nt < 8; nt++) {
            s[nt][0] *= SCALE; s[nt][1] *= SCALE; s[nt][2] *= SCALE; s[nt][3] *= SCALE;
            mx0 = fmaxf(mx0, fmaxf(s[nt][0], s[nt][1]));
            mx1 = fmaxf(mx1, fmaxf(s[nt][2], s[nt][3]));
        }
        #pragma unroll
        for (int off = 1; off <= 2; off <<= 1) {
            mx0 = fmaxf(mx0, __shfl_xor_sync(0xffffffffu, mx0, off));
            mx1 = fmaxf(mx1, __shfl_xor_sync(0xffffffffu, mx1, off));
        }
        float nm0 = fmaxf(m0, mx0), nm1 = fmaxf(m1, mx1);
        float f0 = __expf(m0 - nm0), f1 = __expf(m1 - nm1);
        m0 = nm0; m1 = nm1;
        float rs0 = 0.f, rs1 = 0.f;
        #pragma unroll
        for (int nt = 0; nt < 8; nt++) {
            float p0 = __expf(s[nt][0] - m0);
            float p1 = __expf(s[nt][1] - m0);
            float p2 = __expf(s[nt][2] - m1);
            float p3 = __expf(s[nt][3] - m1);
            rs0 += p0 + p1; rs1 += p2 + p3;
            *(float2*)(Ps + g * PS_PAD + nt * 8 + 2 * tg)       = make_float2(to_tf32(p0), to_tf32(p1));
            *(float2*)(Ps + (g + 8) * PS_PAD + nt * 8 + 2 * tg) = make_float2(to_tf32(p2), to_tf32(p3));
        }
        #pragma unroll
        for (int off = 1; off <= 2; off <<= 1) {
            rs0 += __shfl_xor_sync(0xffffffffu, rs0, off);
            rs1 += __shfl_xor_sync(0xffffffffu, rs1, off);
        }
        l0 = l0 * f0 + rs0;
        l1 = l1 * f1 + rs1;
        #pragma unroll
        for (int nt = 0; nt < 4; nt++) {
            o[nt][0] *= f0; o[nt][1] *= f0; o[nt][2] *= f1; o[nt][3] *= f1;
        }
        __syncwarp();
        #pragma unroll
        for (int kc = 0; kc < 8; kc++) {
            uint32_t a0 = __float_as_uint(Ps[g * PS_PAD + 8 * kc + tg]);
            uint32_t a1 = __float_as_uint(Ps[(g + 8) * PS_PAD + 8 * kc + tg]);
            uint32_t a2 = __float_as_uint(Ps[g * PS_PAD + 8 * kc + tg + 4]);
            uint32_t a3 = __float_as_uint(Ps[(g + 8) * PS_PAD + 8 * kc + tg + 4]);
            #pragma unroll
            for (int nt = 0; nt < 4; nt++) {
                uint32_t b0 = __float_as_uint(Vs[(8 * kc + tg) * VS_PAD + 8 * nt + g]);
                uint32_t b1 = __float_as_uint(Vs[(8 * kc + tg + 4) * VS_PAD + 8 * nt + g]);
                asm volatile(
                    "mma.sync.aligned.m16n8k8.row.col.f32.tf32.tf32.f32 "
                    "{%0,%1,%2,%3}, {%4,%5,%6,%7}, {%8,%9}, {%0,%1,%2,%3};"
                    : "+f"(o[nt][0]), "+f"(o[nt][1]), "+f"(o[nt][2]), "+f"(o[nt][3])
                    : "r"(a0), "r"(a1), "r"(a2), "r"(a3), "r"(b0), "r"(b1));
            }
        }
        __syncthreads();
    }

    float inv0 = 1.f / l0, inv1 = 1.f / l1;
    #pragma unroll
    for (int nt = 0; nt < 4; nt++) {
        int cc = h * DHEAD + nt * 8 + 2 * tg;
        int r0 = b * NNODE + qrow0 + g;
        *(float2*)&ao[(size_t)r0 * CCH + cc] = make_float2(o[nt][0] * inv0, o[nt][1] * inv0);
        *(float2*)&ao[(size_t)(r0 + 8) * CCH + cc] = make_float2(o[nt][2] * inv1, o[nt][3] * inv1);
    }
}

// ---------------- combine: out1 = BN1(h1) + BN2(h2) ----------------
__global__ void k_combine(const float* __restrict__ h1, const float* __restrict__ h2,
                          const float* __restrict__ g1, const float* __restrict__ b1,
                          const float* __restrict__ g2, const float* __restrict__ b2,
                          float* __restrict__ out1)
{
    int i = blockIdx.x * blockDim.x + threadIdx.x;
    if (i >= NTN * CCH / 4) return;
    int c0 = (i & 31) * 4;
    float4 a = ((const float4*)h1)[i];
    float4 bb = ((const float4*)h2)[i];
    float av[4] = { a.x, a.y, a.z, a.w };
    float bv[4] = { bb.x, bb.y, bb.z, bb.w };
    float rv[4];
    const float invn = 1.f / (float)NTN;
    #pragma unroll
    for (int j = 0; j < 4; j++) {
        int c = c0 + j;
        float m1 = d_stats[c] * invn;
        float v1 = d_stats[CCH + c] * invn - m1 * m1;
        float k1 = rsqrtf(v1 + EPSBN) * g1[c];
        float m2 = d_stats[2 * CCH + c] * invn;
        float v2 = d_stats[3 * CCH + c] * invn - m2 * m2;
        float k2 = rsqrtf(v2 + EPSBN) * g2[c];
        rv[j] = (av[j] - m1) * k1 + b1[c] + (bv[j] - m2) * k2 + b2[c];
    }
    ((float4*)out1)[i] = make_float4(rv[0], rv[1], rv[2], rv[3]);
}

// ---------------- final: out = BN3(out2) ----------------
__global__ void k_final(const float* __restrict__ src,
                        const float* __restrict__ g3, const float* __restrict__ b3,
                        float* __restrict__ out)
{
    int i = blockIdx.x * blockDim.x + threadIdx.x;
    if (i >= NTN * CCH / 4) return;
    int c0 = (i & 31) * 4;
    float4 a = ((const float4*)src)[i];
    float av[4] = { a.x, a.y, a.z, a.w };
    float rv[4];
    const float invn = 1.f / (float)NTN;
    #pragma unroll
    for (int j = 0; j < 4; j++) {
        int c = c0 + j;
        float m = d_stats[4 * CCH + c] * invn;
        float v = d_stats[5 * CCH + c] * invn - m * m;
        float k = rsqrtf(v + EPSBN) * g3[c];
        rv[j] = (av[j] - m) * k + b3[c];
    }
    ((float4*)out)[i] = make_float4(rv[0], rv[1], rv[2], rv[3]);
}

// ---------------- host launcher ----------------
extern "C" void kernel_launch(void* const* d_in, const int* in_sizes, int n_in,
                              void* d_out, int out_size)
{
    const float* x    = (const float*)d_in[0];
    const int*   ei   = (const int*)d_in[1];
    const float* Wc   = (const float*)d_in[2];
    const float* bc   = (const float*)d_in[3];
    const float* Winp = (const float*)d_in[4];
    const float* binp = (const float*)d_in[5];
    const float* Wout = (const float*)d_in[6];
    const float* bout = (const float*)d_in[7];
    const float* gn1  = (const float*)d_in[8];
    const float* bn1  = (const float*)d_in[9];
    const float* gn2  = (const float*)d_in[10];
    const float* bn2  = (const float*)d_in[11];
    const float* gn3  = (const float*)d_in[12];
    const float* bn3  = (const float*)d_in[13];
    const float* Wm1  = (const float*)d_in[14];
    const float* bm1  = (const float*)d_in[15];
    const float* Wm2  = (const float*)d_in[16];
    const float* bm2  = (const float*)d_in[17];
    float* out = (float*)d_out;

    float *agg, *h1, *qkv, *ao, *h2, *out1, *hid, *out2, *stats;
    cudaGetSymbolAddress((void**)&agg,  d_agg);
    cudaGetSymbolAddress((void**)&h1,   d_h1);
    cudaGetSymbolAddress((void**)&qkv,  d_qkv);
    cudaGetSymbolAddress((void**)&ao,   d_ao);
    cudaGetSymbolAddress((void**)&h2,   d_h2);
    cudaGetSymbolAddress((void**)&out1, d_out1);
    cudaGetSymbolAddress((void**)&hid,  d_hid);
    cudaGetSymbolAddress((void**)&out2, d_out2);
    cudaGetSymbolAddress((void**)&stats, d_stats);

    cudaFuncSetAttribute(k_attn_tc, cudaFuncAttributeMaxDynamicSharedMemorySize, ATTN_SMEM);

    // --- CSR prologue; qkv GEMM moved to launch index 3 so ncu captures it ---
    k_init<<<NTN / 256, 256>>>();
    k_count<<<NEDGE / 256, 256>>>(ei);
    k_scan<<<1, 1024>>>();
    k_gemm2<<<dim3(NTN / 128, 3), 512>>>(x, Winp, binp, nullptr, qkv, nullptr, nullptr,
                                         NTN, 384, 128, 0);
    k_bin<<<NEDGE / 256, 256>>>(ei);
    k_agg<<<NTN * 32 / 256, 256>>>(x);

    // --- local branch: h1 = agg @ Wc^T + bc + x ; fused stats1 ---
    k_gemm2<<<dim3(NTN / 128, 1), 512>>>(agg, Wc, bc, x, h1, stats, stats + CCH,
                                         NTN, 128, 128, 0);

    // --- global branch ---
    k_attn_tc<<<BATCH * NH * 4, 256, ATTN_SMEM>>>(qkv, ao);
    k_gemm2<<<dim3(NTN / 128, 1), 512>>>(ao, Wout, bout, x, h2, stats + 2 * CCH, stats + 3 * CCH,
                                         NTN, 128, 128, 0);

    // --- combine + MLP + final BN ---
    k_combine<<<NTN * CCH / 4 / 256, 256>>>(h1, h2, gn1, bn1, gn2, bn2, out1);
    k_gemm2<<<dim3(NTN / 128, 2), 512>>>(out1, Wm1, bm1, nullptr, hid, nullptr, nullptr,
                                         NTN, 256, 128, 1);
    k_gemm2<<<dim3(NTN / 128, 1), 512>>>(hid, Wm2, bm2, out1, out2, stats + 4 * CCH, stats + 5 * CCH,
                                         NTN, 128, 256, 0);
    k_final<<<NTN * CCH / 4 / 256, 256>>>(out2, gn3, bn3, out);
}

// round 13
// speedup vs baseline: 1.1091x; 1.1091x over previous
#include <cuda_runtime.h>
#include <cstdint>
#include <cstddef>

#define NTN   32768
#define CCH   128
#define BATCH 64
#define NNODE 512
#define NH    4
#define DHEAD 32
#define NEDGE 524288
#define EPSBN 1e-5f

// ---------------- scratch (static device globals; no allocation) ----------------
__device__ int   d_cnt[NTN];
__device__ int   d_offs[NTN + 1];
__device__ int   d_cursor[NTN];
__device__ int   d_ebin[NEDGE];
__device__ float d_agg[NTN * CCH];
__device__ float d_h1[NTN * CCH];
__device__ float d_qkv[NTN * 3 * CCH];
__device__ float d_ao[NTN * CCH];
__device__ float d_h2[NTN * CCH];
__device__ float d_out1[NTN * CCH];
__device__ float d_hid[NTN * 2 * CCH];
__device__ float d_out2[NTN * CCH];
__device__ float d_stats[6 * CCH];

// ---------------- init ----------------
__global__ void k_init() {
    int i = blockIdx.x * blockDim.x + threadIdx.x;
    if (i < NTN) d_cnt[i] = 0;
    if (i < 6 * CCH) d_stats[i] = 0.f;
}

__global__ void k_count(const int* __restrict__ ei) {
    int e = blockIdx.x * blockDim.x + threadIdx.x;
    if (e < NEDGE) atomicAdd(&d_cnt[ei[NEDGE + e]], 1);
}

__global__ void k_scan() {
    __shared__ int part[1024];
    int tid = threadIdx.x;
    int base = tid * 32;
    int local[32];
    int s = 0;
    #pragma unroll
    for (int i = 0; i < 32; i++) { local[i] = d_cnt[base + i]; s += local[i]; }
    part[tid] = s;
    __syncthreads();
    for (int off = 1; off < 1024; off <<= 1) {
        int v = (tid >= off) ? part[tid - off] : 0;
        __syncthreads();
        part[tid] += v;
        __syncthreads();
    }
    int run = (tid == 0) ? 0 : part[tid - 1];
    #pragma unroll
    for (int i = 0; i < 32; i++) {
        d_offs[base + i] = run;
        d_cursor[base + i] = run;
        run += local[i];
    }
    if (tid == 1023) d_offs[NTN] = run;
}

__global__ void k_bin(const int* __restrict__ ei) {
    int e = blockIdx.x * blockDim.x + threadIdx.x;
    if (e < NEDGE) {
        int src = ei[e];
        int dst = ei[NEDGE + e];
        int pos = atomicAdd(&d_cursor[dst], 1);
        d_ebin[pos] = src;
    }
}

__global__ void k_agg(const float* __restrict__ x) {
    int warp = (blockIdx.x * blockDim.x + threadIdx.x) >> 5;
    int lane = threadIdx.x & 31;
    if (warp >= NTN) return;
    int beg = d_offs[warp], end = d_offs[warp + 1];
    const float4* x4 = (const float4*)x;
    float4 acc = make_float4(0.f, 0.f, 0.f, 0.f);
    for (int e = beg; e < end; e++) {
        int s = __ldg(&d_ebin[e]);
        float4 v = x4[(size_t)s * 32 + lane];
        acc.x += v.x; acc.y += v.y; acc.z += v.z; acc.w += v.w;
    }
    int deg = end - beg;
    float inv = 1.f / (float)(deg > 0 ? deg : 1);
    acc.x *= inv; acc.y *= inv; acc.z *= inv; acc.w *= inv;
    ((float4*)d_agg)[(size_t)warp * 32 + lane] = acc;
}

// ---------------- tf32 helper ----------------
__device__ __forceinline__ float to_tf32(float x) {
    uint32_t u;
    asm("cvt.rna.tf32.f32 %0, %1;" : "=r"(u) : "f"(x));
    return __uint_as_float(u);
}

// ---------------- tf32 GEMM: 128x128 CTA, 256 thr, 64x32 warp tile ----------------
// Double-buffered smem (GBK=16): fill of next k-tile overlaps MMA of current.
// out[M,NC] = A[M,K] @ W[NC,K]^T + bias (+resid)(+relu)(+col stats)
#define GBK 16
#define GPAD 20
__global__ void __launch_bounds__(256) k_gemm2(
    const float* __restrict__ A, const float* __restrict__ W,
    const float* __restrict__ bias, const float* __restrict__ resid,
    float* __restrict__ out, float* __restrict__ ssum, float* __restrict__ ssq,
    int M, int NC, int K, int relu)
{
    __shared__ float As[2][128][GPAD];
    __shared__ float Bs[2][128][GPAD];
    int row0 = blockIdx.x * 128;
    int col0 = blockIdx.y * 128;
    int tid = threadIdx.x;
    int wid = tid >> 5;
    int lane = tid & 31;
    int g = lane >> 2, tg = lane & 3;
    int wm = (wid & 1) * 64;          // 2 warp-rows of 64
    int wn = (wid >> 1) * 32;         // 4 warp-cols of 32

    int m_base = tid >> 2;            // 0..63
    int kq = (tid & 3) * 4;           // 0,4,8,12

    float c[4][4][4];
    #pragma unroll
    for (int i = 0; i < 4; i++)
        #pragma unroll
        for (int j = 0; j < 4; j++)
            #pragma unroll
            for (int l = 0; l < 4; l++) c[i][j][l] = 0.f;

    // fill buffer 0 with k-tile 0
    #pragma unroll
    for (int it = 0; it < 2; it++) {
        int m = m_base + it * 64;
        float4 v = *(const float4*)&A[(size_t)(row0 + m) * K + kq];
        v.x = to_tf32(v.x); v.y = to_tf32(v.y); v.z = to_tf32(v.z); v.w = to_tf32(v.w);
        *(float4*)&As[0][m][kq] = v;
        float4 w = *(const float4*)&W[(size_t)(col0 + m) * K + kq];
        w.x = to_tf32(w.x); w.y = to_tf32(w.y); w.z = to_tf32(w.z); w.w = to_tf32(w.w);
        *(float4*)&Bs[0][m][kq] = w;
    }
    __syncthreads();

    int cur = 0;
    for (int kb = 0; kb < K; kb += GBK) {
        // fill next buffer (overlaps with MMA below; no hazard: other buffer)
        if (kb + GBK < K) {
            int nxt = cur ^ 1;
            #pragma unroll
            for (int it = 0; it < 2; it++) {
                int m = m_base + it * 64;
                float4 v = *(const float4*)&A[(size_t)(row0 + m) * K + kb + GBK + kq];
                v.x = to_tf32(v.x); v.y = to_tf32(v.y); v.z = to_tf32(v.z); v.w = to_tf32(v.w);
                *(float4*)&As[nxt][m][kq] = v;
                float4 w = *(const float4*)&W[(size_t)(col0 + m) * K + kb + GBK + kq];
                w.x = to_tf32(w.x); w.y = to_tf32(w.y); w.z = to_tf32(w.z); w.w = to_tf32(w.w);
                *(float4*)&Bs[nxt][m][kq] = w;
            }
        }
        // MMA on current buffer: 2 k-slices of 8
        #pragma unroll
        for (int ks = 0; ks < 2; ks++) {
            int k0 = ks * 8;
            uint32_t b[4][2];
            #pragma unroll
            for (int nt = 0; nt < 4; nt++) {
                int n = wn + nt * 8 + g;
                b[nt][0] = __float_as_uint(Bs[cur][n][k0 + tg]);
                b[nt][1] = __float_as_uint(Bs[cur][n][k0 + tg + 4]);
            }
            #pragma unroll
            for (int mt = 0; mt < 4; mt++) {
                int m = wm + mt * 16 + g;
                uint32_t a0 = __float_as_uint(As[cur][m][k0 + tg]);
                uint32_t a1 = __float_as_uint(As[cur][m + 8][k0 + tg]);
                uint32_t a2 = __float_as_uint(As[cur][m][k0 + tg + 4]);
                uint32_t a3 = __float_as_uint(As[cur][m + 8][k0 + tg + 4]);
                #pragma unroll
                for (int nt = 0; nt < 4; nt++) {
                    asm volatile(
                        "mma.sync.aligned.m16n8k8.row.col.f32.tf32.tf32.f32 "
                        "{%0,%1,%2,%3}, {%4,%5,%6,%7}, {%8,%9}, {%0,%1,%2,%3};"
                        : "+f"(c[mt][nt][0]), "+f"(c[mt][nt][1]),
                          "+f"(c[mt][nt][2]), "+f"(c[mt][nt][3])
                        : "r"(a0), "r"(a1), "r"(a2), "r"(a3),
                          "r"(b[nt][0]), "r"(b[nt][1]));
                }
            }
        }
        __syncthreads();
        cur ^= 1;
    }

    // epilogue (+optional fused column stats)
    float s0[4] = {0.f, 0.f, 0.f, 0.f}, s1[4] = {0.f, 0.f, 0.f, 0.f};
    float q0[4] = {0.f, 0.f, 0.f, 0.f}, q1[4] = {0.f, 0.f, 0.f, 0.f};
    #pragma unroll
    for (int mt = 0; mt < 4; mt++) {
        #pragma unroll
        for (int nt = 0; nt < 4; nt++) {
            int r = row0 + wm + mt * 16 + g;
            int cc = col0 + wn + nt * 8 + 2 * tg;
            float2 bv = *(const float2*)&bias[cc];
            float v0 = c[mt][nt][0] + bv.x;
            float v1 = c[mt][nt][1] + bv.y;
            float v2 = c[mt][nt][2] + bv.x;
            float v3 = c[mt][nt][3] + bv.y;
            if (resid) {
                float2 r0v = *(const float2*)&resid[(size_t)r * NC + cc];
                float2 r1v = *(const float2*)&resid[(size_t)(r + 8) * NC + cc];
                v0 += r0v.x; v1 += r0v.y; v2 += r1v.x; v3 += r1v.y;
            }
            if (relu) {
                v0 = fmaxf(v0, 0.f); v1 = fmaxf(v1, 0.f);
                v2 = fmaxf(v2, 0.f); v3 = fmaxf(v3, 0.f);
            }
            *(float2*)&out[(size_t)r * NC + cc] = make_float2(v0, v1);
            *(float2*)&out[(size_t)(r + 8) * NC + cc] = make_float2(v2, v3);
            if (ssum) {
                s0[nt] += v0 + v2;
                s1[nt] += v1 + v3;
                q0[nt] += v0 * v0 + v2 * v2;
                q1[nt] += v1 * v1 + v3 * v3;
            }
        }
    }
    if (ssum) {
        #pragma unroll
        for (int nt = 0; nt < 4; nt++) {
            #pragma unroll
            for (int off = 4; off <= 16; off <<= 1) {
                s0[nt] += __shfl_xor_sync(0xffffffffu, s0[nt], off);
                s1[nt] += __shfl_xor_sync(0xffffffffu, s1[nt], off);
                q0[nt] += __shfl_xor_sync(0xffffffffu, q0[nt], off);
                q1[nt] += __shfl_xor_sync(0xffffffffu, q1[nt], off);
            }
            if (lane < 4) {
                int cc = col0 + wn + nt * 8 + 2 * tg;
                atomicAdd(&ssum[cc], s0[nt]);
                atomicAdd(&ssq[cc],  q0[nt]);
                atomicAdd(&ssum[cc + 1], s1[nt]);
                atomicAdd(&ssq[cc + 1],  q1[nt]);
            }
        }
    }
}

// ---------------- tensor-core flash attention (validated R5) ----------------
#define KT 64
#define KS_PAD 36
#define VS_PAD 40
#define PS_PAD 68
#define ATTN_SMEM ((KT * KS_PAD + KT * VS_PAD + 8 * 16 * PS_PAD) * 4)
__global__ void __launch_bounds__(256) k_attn_tc(const float* __restrict__ qkv,
                                                 float* __restrict__ ao)
{
    extern __shared__ float sm[];
    float* Ks = sm;
    float* Vs = Ks + KT * KS_PAD;
    int tid = threadIdx.x;
    int wid = tid >> 5;
    int lane = tid & 31;
    int g = lane >> 2, tg = lane & 3;
    float* Ps = Vs + KT * VS_PAD + wid * 16 * PS_PAD;

    int blk = blockIdx.x;
    int qt = blk & 3;
    int bh = blk >> 2;
    int b = bh >> 2;
    int h = bh & 3;
    const float* base = qkv + (size_t)b * NNODE * (3 * CCH);
    int qrow0 = qt * 128 + wid * 16;
    const float SCALE = 0.1767766952966369f;

    uint32_t qa[4][4];
    #pragma unroll
    for (int kc = 0; kc < 4; kc++) {
        const float* q0 = base + (size_t)(qrow0 + g) * (3 * CCH) + h * DHEAD + 8 * kc;
        const float* q1 = base + (size_t)(qrow0 + g + 8) * (3 * CCH) + h * DHEAD + 8 * kc;
        qa[kc][0] = __float_as_uint(to_tf32(q0[tg]));
        qa[kc][1] = __float_as_uint(to_tf32(q1[tg]));
        qa[kc][2] = __float_as_uint(to_tf32(q0[tg + 4]));
        qa[kc][3] = __float_as_uint(to_tf32(q1[tg + 4]));
    }

    float m0 = -1e30f, m1 = -1e30f, l0 = 0.f, l1 = 0.f;
    float o[4][4];
    #pragma unroll
    for (int i = 0; i < 4; i++)
        #pragma unroll
        for (int j = 0; j < 4; j++) o[i][j] = 0.f;

    for (int kt = 0; kt < NNODE / KT; kt++) {
        #pragma unroll
        for (int it = 0; it < 2; it++) {
            int idx = tid + it * 256;
            int row = idx >> 3;
            int c4 = (idx & 7) * 4;
            const float* krow = base + (size_t)(kt * KT + row) * (3 * CCH) + CCH + h * DHEAD;
            const float* vrow = base + (size_t)(kt * KT + row) * (3 * CCH) + 2 * CCH + h * DHEAD;
            float4 kv = *(const float4*)(krow + c4);
            float4 vv = *(const float4*)(vrow + c4);
            kv.x = to_tf32(kv.x); kv.y = to_tf32(kv.y); kv.z = to_tf32(kv.z); kv.w = to_tf32(kv.w);
            vv.x = to_tf32(vv.x); vv.y = to_tf32(vv.y); vv.z = to_tf32(vv.z); vv.w = to_tf32(vv.w);
            *(float4*)(Ks + row * KS_PAD + c4) = kv;
            *(float4*)(Vs + row * VS_PAD + c4) = vv;
        }
        __syncthreads();

        float s[8][4];
        #pragma unroll
        for (int nt = 0; nt < 8; nt++)
            #pragma unroll
            for (int j = 0; j < 4; j++) s[nt][j] = 0.f;
        #pragma unroll
        for (int kc = 0; kc < 4; kc++) {
            #pragma unroll
            for (int nt = 0; nt < 8; nt++) {
                uint32_t b0 = __float_as_uint(Ks[(nt * 8 + g) * KS_PAD + 8 * kc + tg]);
                uint32_t b1 = __float_as_uint(Ks[(nt * 8 + g) * KS_PAD + 8 * kc + tg + 4]);
                asm volatile(
                    "mma.sync.aligned.m16n8k8.row.col.f32.tf32.tf32.f32 "
                    "{%0,%1,%2,%3}, {%4,%5,%6,%7}, {%8,%9}, {%0,%1,%2,%3};"
                    : "+f"(s[nt][0]), "+f"(s[nt][1]), "+f"(s[nt][2]), "+f"(s[nt][3])
                    : "r"(qa[kc][0]), "r"(qa[kc][1]), "r"(qa[kc][2]), "r"(qa[kc][3]),
                      "r"(b0), "r"(b1));
            }
        }
        float mx0 = -1e30f, mx1 = -1e30f;
        #pragma unroll
        for (int nt = 0; nt < 8; nt++) {
            s[nt][0] *= SCALE; s[nt][1] *= SCALE; s[nt][2] *= SCALE; s[nt][3] *= SCALE;
            mx0 = fmaxf(mx0, fmaxf(s[nt][0], s[nt][1]));
            mx1 = fmaxf(mx1, fmaxf(s[nt][2], s[nt][3]));
        }
        #pragma unroll
        for (int off = 1; off <= 2; off <<= 1) {
            mx0 = fmaxf(mx0, __shfl_xor_sync(0xffffffffu, mx0, off));
            mx1 = fmaxf(mx1, __shfl_xor_sync(0xffffffffu, mx1, off));
        }
        float nm0 = fmaxf(m0, mx0), nm1 = fmaxf(m1, mx1);
        float f0 = __expf(m0 - nm0), f1 = __expf(m1 - nm1);
        m0 = nm0; m1 = nm1;
        float rs0 = 0.f, rs1 = 0.f;
        #pragma unroll
        for (int nt = 0; nt < 8; nt++) {
            float p0 = __expf(s[nt][0] - m0);
            float p1 = __expf(s[nt][1] - m0);
            float p2 = __expf(s[nt][2] - m1);
            float p3 = __expf(s[nt][3] - m1);
            rs0 += p0 + p1; rs1 += p2 + p3;
            *(float2*)(Ps + g * PS_PAD + nt * 8 + 2 * tg)       = make_float2(to_tf32(p0), to_tf32(p1));
            *(float2*)(Ps + (g + 8) * PS_PAD + nt * 8 + 2 * tg) = make_float2(to_tf32(p2), to_tf32(p3));
        }
        #pragma unroll
        for (int off = 1; off <= 2; off <<= 1) {
            rs0 += __shfl_xor_sync(0xffffffffu, rs0, off);
            rs1 += __shfl_xor_sync(0xffffffffu, rs1, off);
        }
        l0 = l0 * f0 + rs0;
        l1 = l1 * f1 + rs1;
        #pragma unroll
        for (int nt = 0; nt < 4; nt++) {
            o[nt][0] *= f0; o[nt][1] *= f0; o[nt][2] *= f1; o[nt][3] *= f1;
        }
        __syncwarp();
        #pragma unroll
        for (int kc = 0; kc < 8; kc++) {
            uint32_t a0 = __float_as_uint(Ps[g * PS_PAD + 8 * kc + tg]);
            uint32_t a1 = __float_as_uint(Ps[(g + 8) * PS_PAD + 8 * kc + tg]);
            uint32_t a2 = __float_as_uint(Ps[g * PS_PAD + 8 * kc + tg + 4]);
            uint32_t a3 = __float_as_uint(Ps[(g + 8) * PS_PAD + 8 * kc + tg + 4]);
            #pragma unroll
            for (int nt = 0; nt < 4; nt++) {
                uint32_t b0 = __float_as_uint(Vs[(8 * kc + tg) * VS_PAD + 8 * nt + g]);
                uint32_t b1 = __float_as_uint(Vs[(8 * kc + tg + 4) * VS_PAD + 8 * nt + g]);
                asm volatile(
                    "mma.sync.aligned.m16n8k8.row.col.f32.tf32.tf32.f32 "
                    "{%0,%1,%2,%3}, {%4,%5,%6,%7}, {%8,%9}, {%0,%1,%2,%3};"
                    : "+f"(o[nt][0]), "+f"(o[nt][1]), "+f"(o[nt][2]), "+f"(o[nt][3])
                    : "r"(a0), "r"(a1), "r"(a2), "r"(a3), "r"(b0), "r"(b1));
            }
        }
        __syncthreads();
    }

    float inv0 = 1.f / l0, inv1 = 1.f / l1;
    #pragma unroll
    for (int nt = 0; nt < 4; nt++) {
        int cc = h * DHEAD + nt * 8 + 2 * tg;
        int r0 = b * NNODE + qrow0 + g;
        *(float2*)&ao[(size_t)r0 * CCH + cc] = make_float2(o[nt][0] * inv0, o[nt][1] * inv0);
        *(float2*)&ao[(size_t)(r0 + 8) * CCH + cc] = make_float2(o[nt][2] * inv1, o[nt][3] * inv1);
    }
}

// ---------------- combine: out1 = BN1(h1) + BN2(h2) ----------------
__global__ void k_combine(const float* __restrict__ h1, const float* __restrict__ h2,
                          const float* __restrict__ g1, const float* __restrict__ b1,
                          const float* __restrict__ g2, const float* __restrict__ b2,
                          float* __restrict__ out1)
{
    int i = blockIdx.x * blockDim.x + threadIdx.x;
    if (i >= NTN * CCH / 4) return;
    int c0 = (i & 31) * 4;
    float4 a = ((const float4*)h1)[i];
    float4 bb = ((const float4*)h2)[i];
    float av[4] = { a.x, a.y, a.z, a.w };
    float bv[4] = { bb.x, bb.y, bb.z, bb.w };
    float rv[4];
    const float invn = 1.f / (float)NTN;
    #pragma unroll
    for (int j = 0; j < 4; j++) {
        int c = c0 + j;
        float m1 = d_stats[c] * invn;
        float v1 = d_stats[CCH + c] * invn - m1 * m1;
        float k1 = rsqrtf(v1 + EPSBN) * g1[c];
        float m2 = d_stats[2 * CCH + c] * invn;
        float v2 = d_stats[3 * CCH + c] * invn - m2 * m2;
        float k2 = rsqrtf(v2 + EPSBN) * g2[c];
        rv[j] = (av[j] - m1) * k1 + b1[c] + (bv[j] - m2) * k2 + b2[c];
    }
    ((float4*)out1)[i] = make_float4(rv[0], rv[1], rv[2], rv[3]);
}

// ---------------- final: out = BN3(out2) ----------------
__global__ void k_final(const float* __restrict__ src,
                        const float* __restrict__ g3, const float* __restrict__ b3,
                        float* __restrict__ out)
{
    int i = blockIdx.x * blockDim.x + threadIdx.x;
    if (i >= NTN * CCH / 4) return;
    int c0 = (i & 31) * 4;
    float4 a = ((const float4*)src)[i];
    float av[4] = { a.x, a.y, a.z, a.w };
    float rv[4];
    const float invn = 1.f / (float)NTN;
    #pragma unroll
    for (int j = 0; j < 4; j++) {
        int c = c0 + j;
        float m = d_stats[4 * CCH + c] * invn;
        float v = d_stats[5 * CCH + c] * invn - m * m;
        float k = rsqrtf(v + EPSBN) * g3[c];
        rv[j] = (av[j] - m) * k + b3[c];
    }
    ((float4*)out)[i] = make_float4(rv[0], rv[1], rv[2], rv[3]);
}

// ---------------- host launcher ----------------
extern "C" void kernel_launch(void* const* d_in, const int* in_sizes, int n_in,
                              void* d_out, int out_size)
{
    const float* x    = (const float*)d_in[0];
    const int*   ei   = (const int*)d_in[1];
    const float* Wc   = (const float*)d_in[2];
    const float* bc   = (const float*)d_in[3];
    const float* Winp = (const float*)d_in[4];
    const float* binp = (const float*)d_in[5];
    const float* Wout = (const float*)d_in[6];
    const float* bout = (const float*)d_in[7];
    const float* gn1  = (const float*)d_in[8];
    const float* bn1  = (const float*)d_in[9];
    const float* gn2  = (const float*)d_in[10];
    const float* bn2  = (const float*)d_in[11];
    const float* gn3  = (const float*)d_in[12];
    const float* bn3  = (const float*)d_in[13];
    const float* Wm1  = (const float*)d_in[14];
    const float* bm1  = (const float*)d_in[15];
    const float* Wm2  = (const float*)d_in[16];
    const float* bm2  = (const float*)d_in[17];
    float* out = (float*)d_out;

    float *agg, *h1, *qkv, *ao, *h2, *out1, *hid, *out2, *stats;
    cudaGetSymbolAddress((void**)&agg,  d_agg);
    cudaGetSymbolAddress((void**)&h1,   d_h1);
    cudaGetSymbolAddress((void**)&qkv,  d_qkv);
    cudaGetSymbolAddress((void**)&ao,   d_ao);
    cudaGetSymbolAddress((void**)&h2,   d_h2);
    cudaGetSymbolAddress((void**)&out1, d_out1);
    cudaGetSymbolAddress((void**)&hid,  d_hid);
    cudaGetSymbolAddress((void**)&out2, d_out2);
    cudaGetSymbolAddress((void**)&stats, d_stats);

    cudaFuncSetAttribute(k_attn_tc, cudaFuncAttributeMaxDynamicSharedMemorySize, ATTN_SMEM);

    // --- CSR prologue; qkv GEMM at launch index 3 so ncu captures it ---
    k_init<<<NTN / 256, 256>>>();
    k_count<<<NEDGE / 256, 256>>>(ei);
    k_scan<<<1, 1024>>>();
    k_gemm2<<<dim3(NTN / 128, 3), 256>>>(x, Winp, binp, nullptr, qkv, nullptr, nullptr,
                                         NTN, 384, 128, 0);
    k_bin<<<NEDGE / 256, 256>>>(ei);
    k_agg<<<NTN * 32 / 256, 256>>>(x);

    // --- local branch: h1 = agg @ Wc^T + bc + x ; fused stats1 ---
    k_gemm2<<<dim3(NTN / 128, 1), 256>>>(agg, Wc, bc, x, h1, stats, stats + CCH,
                                         NTN, 128, 128, 0);

    // --- global branch ---
    k_attn_tc<<<BATCH * NH * 4, 256, ATTN_SMEM>>>(qkv, ao);
    k_gemm2<<<dim3(NTN / 128, 1), 256>>>(ao, Wout, bout, x, h2, stats + 2 * CCH, stats + 3 * CCH,
                                         NTN, 128, 128, 0);

    // --- combine + MLP + final BN ---
    k_combine<<<NTN * CCH / 4 / 256, 256>>>(h1, h2, gn1, bn1, gn2, bn2, out1);
    k_gemm2<<<dim3(NTN / 128, 2), 256>>>(out1, Wm1, bm1, nullptr, hid, nullptr, nullptr,
                                         NTN, 256, 128, 1);
    k_gemm2<<<dim3(NTN / 128, 1), 256>>>(hid, Wm2, bm2, out1, out2, stats + 4 * CCH, stats + 5 * CCH,
                                         NTN, 128, 256, 0);
    k_final<<<NTN * CCH / 4 / 256, 256>>>(out2, gn3, bn3, out);
}

// round 15
// speedup vs baseline: 1.4665x; 1.3222x over previous
#include <cuda_runtime.h>
#include <cstdint>
#include <cstddef>

#define NTN   32768
#define CCH   128
#define BATCH 64
#define NNODE 512
#define NH    4
#define DHEAD 32
#define NEDGE 524288
#define EPSBN 1e-5f

// ---------------- scratch (static device globals; no allocation) ----------------
__device__ int   d_cnt[NTN];
__device__ int   d_offs[NTN + 1];
__device__ int   d_cursor[NTN];
__device__ int   d_ebin[NEDGE];
__device__ float d_agg[NTN * CCH];
__device__ float d_h1[NTN * CCH];
__device__ float d_qkv[NTN * 3 * CCH];
__device__ float d_ao[NTN * CCH];
__device__ float d_h2[NTN * CCH];
__device__ float d_out1[NTN * CCH];
__device__ float d_hid[NTN * 2 * CCH];
__device__ float d_out2[NTN * CCH];
__device__ float d_stats[6 * CCH];

// ---------------- init ----------------
__global__ void k_init() {
    int i = blockIdx.x * blockDim.x + threadIdx.x;
    if (i < NTN) d_cnt[i] = 0;
    if (i < 6 * CCH) d_stats[i] = 0.f;
}

__global__ void k_count(const int* __restrict__ ei) {
    int e = blockIdx.x * blockDim.x + threadIdx.x;
    if (e < NEDGE) atomicAdd(&d_cnt[ei[NEDGE + e]], 1);
}

__global__ void k_scan() {
    __shared__ int part[1024];
    int tid = threadIdx.x;
    int base = tid * 32;
    int local[32];
    int s = 0;
    #pragma unroll
    for (int i = 0; i < 32; i++) { local[i] = d_cnt[base + i]; s += local[i]; }
    part[tid] = s;
    __syncthreads();
    for (int off = 1; off < 1024; off <<= 1) {
        int v = (tid >= off) ? part[tid - off] : 0;
        __syncthreads();
        part[tid] += v;
        __syncthreads();
    }
    int run = (tid == 0) ? 0 : part[tid - 1];
    #pragma unroll
    for (int i = 0; i < 32; i++) {
        d_offs[base + i] = run;
        d_cursor[base + i] = run;
        run += local[i];
    }
    if (tid == 1023) d_offs[NTN] = run;
}

__global__ void k_bin(const int* __restrict__ ei) {
    int e = blockIdx.x * blockDim.x + threadIdx.x;
    if (e < NEDGE) {
        int src = ei[e];
        int dst = ei[NEDGE + e];
        int pos = atomicAdd(&d_cursor[dst], 1);
        d_ebin[pos] = src;
    }
}

__global__ void k_agg(const float* __restrict__ x) {
    int warp = (blockIdx.x * blockDim.x + threadIdx.x) >> 5;
    int lane = threadIdx.x & 31;
    if (warp >= NTN) return;
    int beg = d_offs[warp], end = d_offs[warp + 1];
    const float4* x4 = (const float4*)x;
    float4 acc = make_float4(0.f, 0.f, 0.f, 0.f);
    for (int e = beg; e < end; e++) {
        int s = __ldg(&d_ebin[e]);
        float4 v = x4[(size_t)s * 32 + lane];
        acc.x += v.x; acc.y += v.y; acc.z += v.z; acc.w += v.w;
    }
    int deg = end - beg;
    float inv = 1.f / (float)(deg > 0 ? deg : 1);
    acc.x *= inv; acc.y *= inv; acc.z *= inv; acc.w *= inv;
    ((float4*)d_agg)[(size_t)warp * 32 + lane] = acc;
}

// ---------------- tf32 helper ----------------
__device__ __forceinline__ float to_tf32(float x) {
    uint32_t u;
    asm("cvt.rna.tf32.f32 %0, %1;" : "=r"(u) : "f"(x));
    return __uint_as_float(u);
}

// ---------------- tf32 GEMM: 128x128 CTA, 256 thr, 64x32 warp tile ----------------
// Double-buffered smem (GBK=16): fill of next k-tile overlaps MMA of current.
// out[M,NC] = A[M,K] @ W[NC,K]^T + bias (+resid)(+relu)(+col stats)
#define GBK 16
#define GPAD 20
__global__ void __launch_bounds__(256) k_gemm2(
    const float* __restrict__ A, const float* __restrict__ W,
    const float* __restrict__ bias, const float* __restrict__ resid,
    float* __restrict__ out, float* __restrict__ ssum, float* __restrict__ ssq,
    int M, int NC, int K, int relu)
{
    __shared__ float As[2][128][GPAD];
    __shared__ float Bs[2][128][GPAD];
    int row0 = blockIdx.x * 128;
    int col0 = blockIdx.y * 128;
    int tid = threadIdx.x;
    int wid = tid >> 5;
    int lane = tid & 31;
    int g = lane >> 2, tg = lane & 3;
    int wm = (wid & 1) * 64;          // 2 warp-rows of 64
    int wn = (wid >> 1) * 32;         // 4 warp-cols of 32

    int m_base = tid >> 2;            // 0..63
    int kq = (tid & 3) * 4;           // 0,4,8,12

    float c[4][4][4];
    #pragma unroll
    for (int i = 0; i < 4; i++)
        #pragma unroll
        for (int j = 0; j < 4; j++)
            #pragma unroll
            for (int l = 0; l < 4; l++) c[i][j][l] = 0.f;

    // fill buffer 0 with k-tile 0
    #pragma unroll
    for (int it = 0; it < 2; it++) {
        int m = m_base + it * 64;
        float4 v = *(const float4*)&A[(size_t)(row0 + m) * K + kq];
        v.x = to_tf32(v.x); v.y = to_tf32(v.y); v.z = to_tf32(v.z); v.w = to_tf32(v.w);
        *(float4*)&As[0][m][kq] = v;
        float4 w = *(const float4*)&W[(size_t)(col0 + m) * K + kq];
        w.x = to_tf32(w.x); w.y = to_tf32(w.y); w.z = to_tf32(w.z); w.w = to_tf32(w.w);
        *(float4*)&Bs[0][m][kq] = w;
    }
    __syncthreads();

    int cur = 0;
    for (int kb = 0; kb < K; kb += GBK) {
        // fill next buffer (overlaps with MMA below; no hazard: other buffer)
        if (kb + GBK < K) {
            int nxt = cur ^ 1;
            #pragma unroll
            for (int it = 0; it < 2; it++) {
                int m = m_base + it * 64;
                float4 v = *(const float4*)&A[(size_t)(row0 + m) * K + kb + GBK + kq];
                v.x = to_tf32(v.x); v.y = to_tf32(v.y); v.z = to_tf32(v.z); v.w = to_tf32(v.w);
                *(float4*)&As[nxt][m][kq] = v;
                float4 w = *(const float4*)&W[(size_t)(col0 + m) * K + kb + GBK + kq];
                w.x = to_tf32(w.x); w.y = to_tf32(w.y); w.z = to_tf32(w.z); w.w = to_tf32(w.w);
                *(float4*)&Bs[nxt][m][kq] = w;
            }
        }
        // MMA on current buffer: 2 k-slices of 8
        #pragma unroll
        for (int ks = 0; ks < 2; ks++) {
            int k0 = ks * 8;
            uint32_t b[4][2];
            #pragma unroll
            for (int nt = 0; nt < 4; nt++) {
                int n = wn + nt * 8 + g;
                b[nt][0] = __float_as_uint(Bs[cur][n][k0 + tg]);
                b[nt][1] = __float_as_uint(Bs[cur][n][k0 + tg + 4]);
            }
            #pragma unroll
            for (int mt = 0; mt < 4; mt++) {
                int m = wm + mt * 16 + g;
                uint32_t a0 = __float_as_uint(As[cur][m][k0 + tg]);
                uint32_t a1 = __float_as_uint(As[cur][m + 8][k0 + tg]);
                uint32_t a2 = __float_as_uint(As[cur][m][k0 + tg + 4]);
                uint32_t a3 = __float_as_uint(As[cur][m + 8][k0 + tg + 4]);
                #pragma unroll
                for (int nt = 0; nt < 4; nt++) {
                    asm volatile(
                        "mma.sync.aligned.m16n8k8.row.col.f32.tf32.tf32.f32 "
                        "{%0,%1,%2,%3}, {%4,%5,%6,%7}, {%8,%9}, {%0,%1,%2,%3};"
                        : "+f"(c[mt][nt][0]), "+f"(c[mt][nt][1]),
                          "+f"(c[mt][nt][2]), "+f"(c[mt][nt][3])
                        : "r"(a0), "r"(a1), "r"(a2), "r"(a3),
                          "r"(b[nt][0]), "r"(b[nt][1]));
                }
            }
        }
        __syncthreads();
        cur ^= 1;
    }

    // epilogue (+optional fused column stats)
    float s0[4] = {0.f, 0.f, 0.f, 0.f}, s1[4] = {0.f, 0.f, 0.f, 0.f};
    float q0[4] = {0.f, 0.f, 0.f, 0.f}, q1[4] = {0.f, 0.f, 0.f, 0.f};
    #pragma unroll
    for (int mt = 0; mt < 4; mt++) {
        #pragma unroll
        for (int nt = 0; nt < 4; nt++) {
            int r = row0 + wm + mt * 16 + g;
            int cc = col0 + wn + nt * 8 + 2 * tg;
            float2 bv = *(const float2*)&bias[cc];
            float v0 = c[mt][nt][0] + bv.x;
            float v1 = c[mt][nt][1] + bv.y;
            float v2 = c[mt][nt][2] + bv.x;
            float v3 = c[mt][nt][3] + bv.y;
            if (resid) {
                float2 r0v = *(const float2*)&resid[(size_t)r * NC + cc];
                float2 r1v = *(const float2*)&resid[(size_t)(r + 8) * NC + cc];
                v0 += r0v.x; v1 += r0v.y; v2 += r1v.x; v3 += r1v.y;
            }
            if (relu) {
                v0 = fmaxf(v0, 0.f); v1 = fmaxf(v1, 0.f);
                v2 = fmaxf(v2, 0.f); v3 = fmaxf(v3, 0.f);
            }
            *(float2*)&out[(size_t)r * NC + cc] = make_float2(v0, v1);
            *(float2*)&out[(size_t)(r + 8) * NC + cc] = make_float2(v2, v3);
            if (ssum) {
                s0[nt] += v0 + v2;
                s1[nt] += v1 + v3;
                q0[nt] += v0 * v0 + v2 * v2;
                q1[nt] += v1 * v1 + v3 * v3;
            }
        }
    }
    if (ssum) {
        #pragma unroll
        for (int nt = 0; nt < 4; nt++) {
            #pragma unroll
            for (int off = 4; off <= 16; off <<= 1) {
                s0[nt] += __shfl_xor_sync(0xffffffffu, s0[nt], off);
                s1[nt] += __shfl_xor_sync(0xffffffffu, s1[nt], off);
                q0[nt] += __shfl_xor_sync(0xffffffffu, q0[nt], off);
                q1[nt] += __shfl_xor_sync(0xffffffffu, q1[nt], off);
            }
            if (lane < 4) {
                int cc = col0 + wn + nt * 8 + 2 * tg;
                atomicAdd(&ssum[cc], s0[nt]);
                atomicAdd(&ssq[cc],  q0[nt]);
                atomicAdd(&ssum[cc + 1], s1[nt]);
                atomicAdd(&ssq[cc + 1],  q1[nt]);
            }
        }
    }
}

// ---------------- tensor-core flash attention (validated R5) ----------------
#define KT 64
#define KS_PAD 36
#define VS_PAD 40
#define PS_PAD 68
#define ATTN_SMEM ((KT * KS_PAD + KT * VS_PAD + 8 * 16 * PS_PAD) * 4)
__global__ void __launch_bounds__(256) k_attn_tc(const float* __restrict__ qkv,
                                                 float* __restrict__ ao)
{
    extern __shared__ float sm[];
    float* Ks = sm;
    float* Vs = Ks + KT * KS_PAD;
    int tid = threadIdx.x;
    int wid = tid >> 5;
    int lane = tid & 31;
    int g = lane >> 2, tg = lane & 3;
    float* Ps = Vs + KT * VS_PAD + wid * 16 * PS_PAD;

    int blk = blockIdx.x;
    int qt = blk & 3;
    int bh = blk >> 2;
    int b = bh >> 2;
    int h = bh & 3;
    const float* base = qkv + (size_t)b * NNODE * (3 * CCH);
    int qrow0 = qt * 128 + wid * 16;
    const float SCALE = 0.1767766952966369f;

    uint32_t qa[4][4];
    #pragma unroll
    for (int kc = 0; kc < 4; kc++) {
        const float* q0 = base + (size_t)(qrow0 + g) * (3 * CCH) + h * DHEAD + 8 * kc;
        const float* q1 = base + (size_t)(qrow0 + g + 8) * (3 * CCH) + h * DHEAD + 8 * kc;
        qa[kc][0] = __float_as_uint(to_tf32(q0[tg]));
        qa[kc][1] = __float_as_uint(to_tf32(q1[tg]));
        qa[kc][2] = __float_as_uint(to_tf32(q0[tg + 4]));
        qa[kc][3] = __float_as_uint(to_tf32(q1[tg + 4]));
    }

    float m0 = -1e30f, m1 = -1e30f, l0 = 0.f, l1 = 0.f;
    float o[4][4];
    #pragma unroll
    for (int i = 0; i < 4; i++)
        #pragma unroll
        for (int j = 0; j < 4; j++) o[i][j] = 0.f;

    for (int kt = 0; kt < NNODE / KT; kt++) {
        #pragma unroll
        for (int it = 0; it < 2; it++) {
            int idx = tid + it * 256;
            int row = idx >> 3;
            int c4 = (idx & 7) * 4;
            const float* krow = base + (size_t)(kt * KT + row) * (3 * CCH) + CCH + h * DHEAD;
            const float* vrow = base + (size_t)(kt * KT + row) * (3 * CCH) + 2 * CCH + h * DHEAD;
            float4 kv = *(const float4*)(krow + c4);
            float4 vv = *(const float4*)(vrow + c4);
            kv.x = to_tf32(kv.x); kv.y = to_tf32(kv.y); kv.z = to_tf32(kv.z); kv.w = to_tf32(kv.w);
            vv.x = to_tf32(vv.x); vv.y = to_tf32(vv.y); vv.z = to_tf32(vv.z); vv.w = to_tf32(vv.w);
            *(float4*)(Ks + row * KS_PAD + c4) = kv;
            *(float4*)(Vs + row * VS_PAD + c4) = vv;
        }
        __syncthreads();

        float s[8][4];
        #pragma unroll
        for (int nt = 0; nt < 8; nt++)
            #pragma unroll
            for (int j = 0; j < 4; j++) s[nt][j] = 0.f;
        #pragma unroll
        for (int kc = 0; kc < 4; kc++) {
            #pragma unroll
            for (int nt = 0; nt < 8; nt++) {
                uint32_t b0 = __float_as_uint(Ks[(nt * 8 + g) * KS_PAD + 8 * kc + tg]);
                uint32_t b1 = __float_as_uint(Ks[(nt * 8 + g) * KS_PAD + 8 * kc + tg + 4]);
                asm volatile(
                    "mma.sync.aligned.m16n8k8.row.col.f32.tf32.tf32.f32 "
                    "{%0,%1,%2,%3}, {%4,%5,%6,%7}, {%8,%9}, {%0,%1,%2,%3};"
                    : "+f"(s[nt][0]), "+f"(s[nt][1]), "+f"(s[nt][2]), "+f"(s[nt][3])
                    : "r"(qa[kc][0]), "r"(qa[kc][1]), "r"(qa[kc][2]), "r"(qa[kc][3]),
                      "r"(b0), "r"(b1));
            }
        }
        float mx0 = -1e30f, mx1 = -1e30f;
        #pragma unroll
        for (int nt = 0; nt < 8; nt++) {
            s[nt][0] *= SCALE; s[nt][1] *= SCALE; s[nt][2] *= SCALE; s[nt][3] *= SCALE;
            mx0 = fmaxf(mx0, fmaxf(s[nt][0], s[nt][1]));
            mx1 = fmaxf(mx1, fmaxf(s[nt][2], s[nt][3]));
        }
        #pragma unroll
        for (int off = 1; off <= 2; off <<= 1) {
            mx0 = fmaxf(mx0, __shfl_xor_sync(0xffffffffu, mx0, off));
            mx1 = fmaxf(mx1, __shfl_xor_sync(0xffffffffu, mx1, off));
        }
        float nm0 = fmaxf(m0, mx0), nm1 = fmaxf(m1, mx1);
        float f0 = __expf(m0 - nm0), f1 = __expf(m1 - nm1);
        m0 = nm0; m1 = nm1;
        float rs0 = 0.f, rs1 = 0.f;
        #pragma unroll
        for (int nt = 0; nt < 8; nt++) {
            float p0 = __expf(s[nt][0] - m0);
            float p1 = __expf(s[nt][1] - m0);
            float p2 = __expf(s[nt][2] - m1);
            float p3 = __expf(s[nt][3] - m1);
            rs0 += p0 + p1; rs1 += p2 + p3;
            *(float2*)(Ps + g * PS_PAD + nt * 8 + 2 * tg)       = make_float2(to_tf32(p0), to_tf32(p1));
            *(float2*)(Ps + (g + 8) * PS_PAD + nt * 8 + 2 * tg) = make_float2(to_tf32(p2), to_tf32(p3));
        }
        #pragma unroll
        for (int off = 1; off <= 2; off <<= 1) {
            rs0 += __shfl_xor_sync(0xffffffffu, rs0, off);
            rs1 += __shfl_xor_sync(0xffffffffu, rs1, off);
        }
        l0 = l0 * f0 + rs0;
        l1 = l1 * f1 + rs1;
        #pragma unroll
        for (int nt = 0; nt < 4; nt++) {
            o[nt][0] *= f0; o[nt][1] *= f0; o[nt][2] *= f1; o[nt][3] *= f1;
        }
        __syncwarp();
        #pragma unroll
        for (int kc = 0; kc < 8; kc++) {
            uint32_t a0 = __float_as_uint(Ps[g * PS_PAD + 8 * kc + tg]);
            uint32_t a1 = __float_as_uint(Ps[(g + 8) * PS_PAD + 8 * kc + tg]);
            uint32_t a2 = __float_as_uint(Ps[g * PS_PAD + 8 * kc + tg + 4]);
            uint32_t a3 = __float_as_uint(Ps[(g + 8) * PS_PAD + 8 * kc + tg + 4]);
            #pragma unroll
            for (int nt = 0; nt < 4; nt++) {
                uint32_t b0 = __float_as_uint(Vs[(8 * kc + tg) * VS_PAD + 8 * nt + g]);
                uint32_t b1 = __float_as_uint(Vs[(8 * kc + tg + 4) * VS_PAD + 8 * nt + g]);
                asm volatile(
                    "mma.sync.aligned.m16n8k8.row.col.f32.tf32.tf32.f32 "
                    "{%0,%1,%2,%3}, {%4,%5,%6,%7}, {%8,%9}, {%0,%1,%2,%3};"
                    : "+f"(o[nt][0]), "+f"(o[nt][1]), "+f"(o[nt][2]), "+f"(o[nt][3])
                    : "r"(a0), "r"(a1), "r"(a2), "r"(a3), "r"(b0), "r"(b1));
            }
        }
        __syncthreads();
    }

    float inv0 = 1.f / l0, inv1 = 1.f / l1;
    #pragma unroll
    for (int nt = 0; nt < 4; nt++) {
        int cc = h * DHEAD + nt * 8 + 2 * tg;
        int r0 = b * NNODE + qrow0 + g;
        *(float2*)&ao[(size_t)r0 * CCH + cc] = make_float2(o[nt][0] * inv0, o[nt][1] * inv0);
        *(float2*)&ao[(size_t)(r0 + 8) * CCH + cc] = make_float2(o[nt][2] * inv1, o[nt][3] * inv1);
    }
}

// ---------------- combine: out1 = BN1(h1) + BN2(h2) ----------------
__global__ void k_combine(const float* __restrict__ h1, const float* __restrict__ h2,
                          const float* __restrict__ g1, const float* __restrict__ b1,
                          const float* __restrict__ g2, const float* __restrict__ b2,
                          float* __restrict__ out1)
{
    int i = blockIdx.x * blockDim.x + threadIdx.x;
    if (i >= NTN * CCH / 4) return;
    int c0 = (i & 31) * 4;
    float4 a = ((const float4*)h1)[i];
    float4 bb = ((const float4*)h2)[i];
    float av[4] = { a.x, a.y, a.z, a.w };
    float bv[4] = { bb.x, bb.y, bb.z, bb.w };
    float rv[4];
    const float invn = 1.f / (float)NTN;
    #pragma unroll
    for (int j = 0; j < 4; j++) {
        int c = c0 + j;
        float m1 = d_stats[c] * invn;
        float v1 = d_stats[CCH + c] * invn - m1 * m1;
        float k1 = rsqrtf(v1 + EPSBN) * g1[c];
        float m2 = d_stats[2 * CCH + c] * invn;
        float v2 = d_stats[3 * CCH + c] * invn - m2 * m2;
        float k2 = rsqrtf(v2 + EPSBN) * g2[c];
        rv[j] = (av[j] - m1) * k1 + b1[c] + (bv[j] - m2) * k2 + b2[c];
    }
    ((float4*)out1)[i] = make_float4(rv[0], rv[1], rv[2], rv[3]);
}

// ---------------- final: out = BN3(out2) ----------------
__global__ void k_final(const float* __restrict__ src,
                        const float* __restrict__ g3, const float* __restrict__ b3,
                        float* __restrict__ out)
{
    int i = blockIdx.x * blockDim.x + threadIdx.x;
    if (i >= NTN * CCH / 4) return;
    int c0 = (i & 31) * 4;
    float4 a = ((const float4*)src)[i];
    float av[4] = { a.x, a.y, a.z, a.w };
    float rv[4];
    const float invn = 1.f / (float)NTN;
    #pragma unroll
    for (int j = 0; j < 4; j++) {
        int c = c0 + j;
        float m = d_stats[4 * CCH + c] * invn;
        float v = d_stats[5 * CCH + c] * invn - m * m;
        float k = rsqrtf(v + EPSBN) * g3[c];
        rv[j] = (av[j] - m) * k + b3[c];
    }
    ((float4*)out)[i] = make_float4(rv[0], rv[1], rv[2], rv[3]);
}

// ---------------- host launcher ----------------
extern "C" void kernel_launch(void* const* d_in, const int* in_sizes, int n_in,
                              void* d_out, int out_size)
{
    const float* x    = (const float*)d_in[0];
    const int*   ei   = (const int*)d_in[1];
    const float* Wc   = (const float*)d_in[2];
    const float* bc   = (const float*)d_in[3];
    const float* Winp = (const float*)d_in[4];
    const float* binp = (const float*)d_in[5];
    const float* Wout = (const float*)d_in[6];
    const float* bout = (const float*)d_in[7];
    const float* gn1  = (const float*)d_in[8];
    const float* bn1  = (const float*)d_in[9];
    const float* gn2  = (const float*)d_in[10];
    const float* bn2  = (const float*)d_in[11];
    const float* gn3  = (const float*)d_in[12];
    const float* bn3  = (const float*)d_in[13];
    const float* Wm1  = (const float*)d_in[14];
    const float* bm1  = (const float*)d_in[15];
    const float* Wm2  = (const float*)d_in[16];
    const float* bm2  = (const float*)d_in[17];
    float* out = (float*)d_out;

    float *agg, *h1, *qkv, *ao, *h2, *out1, *hid, *out2, *stats;
    cudaGetSymbolAddress((void**)&agg,  d_agg);
    cudaGetSymbolAddress((void**)&h1,   d_h1);
    cudaGetSymbolAddress((void**)&qkv,  d_qkv);
    cudaGetSymbolAddress((void**)&ao,   d_ao);
    cudaGetSymbolAddress((void**)&h2,   d_h2);
    cudaGetSymbolAddress((void**)&out1, d_out1);
    cudaGetSymbolAddress((void**)&hid,  d_hid);
    cudaGetSymbolAddress((void**)&out2, d_out2);
    cudaGetSymbolAddress((void**)&stats, d_stats);

    cudaFuncSetAttribute(k_attn_tc, cudaFuncAttributeMaxDynamicSharedMemorySize, ATTN_SMEM);

    // Fork-join: local branch (CSR+agg+h1) on the capturing legacy stream,
    // global branch (qkv+attn+h2) on a non-blocking side stream.
    // NOTE: stream/events are deliberately NOT destroyed — destroying a stream
    // that participated in an in-progress capture invalidates the capture.
    // kernel_launch runs only ~2x (correctness + capture), so the leak is ~3
    // host objects total, no device memory.
    cudaStream_t s1;
    cudaStreamCreateWithFlags(&s1, cudaStreamNonBlocking);
    cudaEvent_t evInit, evGlobal;
    cudaEventCreateWithFlags(&evInit, cudaEventDisableTiming);
    cudaEventCreateWithFlags(&evGlobal, cudaEventDisableTiming);

    // --- common prologue ---
    k_init<<<NTN / 256, 256>>>();
    cudaEventRecord(evInit, 0);
    cudaStreamWaitEvent(s1, evInit, 0);

    // --- global branch on s1 ---
    k_gemm2<<<dim3(NTN / 128, 3), 256, 0, s1>>>(x, Winp, binp, nullptr, qkv, nullptr, nullptr,
                                                NTN, 384, 128, 0);
    k_attn_tc<<<BATCH * NH * 4, 256, ATTN_SMEM, s1>>>(qkv, ao);
    k_gemm2<<<dim3(NTN / 128, 1), 256, 0, s1>>>(ao, Wout, bout, x, h2,
                                                stats + 2 * CCH, stats + 3 * CCH,
                                                NTN, 128, 128, 0);
    cudaEventRecord(evGlobal, s1);

    // --- local branch on legacy stream (concurrent with s1) ---
    k_count<<<NEDGE / 256, 256>>>(ei);
    k_scan<<<1, 1024>>>();
    k_bin<<<NEDGE / 256, 256>>>(ei);
    k_agg<<<NTN * 32 / 256, 256>>>(x);
    k_gemm2<<<dim3(NTN / 128, 1), 256>>>(agg, Wc, bc, x, h1, stats, stats + CCH,
                                         NTN, 128, 128, 0);

    // --- join ---
    cudaStreamWaitEvent(0, evGlobal, 0);

    // --- combine + MLP + final BN ---
    k_combine<<<NTN * CCH / 4 / 256, 256>>>(h1, h2, gn1, bn1, gn2, bn2, out1);
    k_gemm2<<<dim3(NTN / 128, 2), 256>>>(out1, Wm1, bm1, nullptr, hid, nullptr, nullptr,
                                         NTN, 256, 128, 1);
    k_gemm2<<<dim3(NTN / 128, 1), 256>>>(hid, Wm2, bm2, out1, out2,
                                         stats + 4 * CCH, stats + 5 * CCH,
                                         NTN, 128, 256, 0);
    k_final<<<NTN * CCH / 4 / 256, 256>>>(out2, gn3, bn3, out);
}